// round 8
// baseline (speedup 1.0000x reference)
#include <cuda_runtime.h>

// IDWT_2D (raw-reshape semantics):
//   x: (B=8, C4=256, H=128, W=128) fp32; C4 = 4 subbands (k) x 64 channels (c)
//   out[b][c][2i + (j>=64)][4*(j%64) + m] = sum_k filters[k][0][m>>1][m&1] * x[b][k*64+c][i][j]
//
// One thread per output float4, ITEMS=4 sites per thread. Sites are strided by
// CHUNK = 2^21 output-float4s = exactly 2 batches: (i,j,c) identical across
// sites, only b += 2s. So all 16 load addresses and 4 store addresses are
// base0/ob0 + compile-time-constant strides -> minimal registers, max occupancy
// at MLP=16. Loads: 16 front-batched LDG.32 (128B/warp each). Stores: 4
// lane-contiguous STG.128 (512B/warp each). .cs streaming: zero reuse.

#define BDIM  256
#define ITEMS 4
#define TOTAL (8 * 64 * 128 * 128)            // output float4 count = 2^23
#define CHUNK (TOTAL / ITEMS)                 // 2^21 = 2 batches of output

__global__ void __launch_bounds__(BDIM) idwt2d_kernel(
    const float* __restrict__ x,
    const float* __restrict__ filt,           // 16 coeffs: [k][a][bb] -> k*4+a*2+bb
    float4*      __restrict__ out)
{
    const int tid = blockIdx.x * BDIM + threadIdx.x;   // in [0, 2^21)

    // Decompose once: tid = ((b0*64 + c)*128 + i)*128 + j, b0 in {0,1}
    const int j = tid & 127;
    int t = tid >> 7;
    const int i = t & 127;
    t >>= 7;
    const int c = t & 63;
    const int b0 = t >> 6;

    const int base0 = ((b0 * 256 + c) * 128 + i) * 128 + j;   // scalar float idx
    const int r     = 2 * i + (j >> 6);
    const int ob0   = ((b0 * 64 + c) * 256 + r) * 64 + (j & 63);

    const int plane   = 64 * 128 * 128;       // subband stride (floats)
    const int SSTRIDE = 2 * 256 * 128 * 128;  // +2 batches in input (floats) = 2^23
    const int OSTRIDE = 2 * 64 * 256 * 64;    // +2 batches in output (float4) = 2^21

    // Front-batched loads: 16 independent LDG.32 in flight
    float v[ITEMS][4];
#pragma unroll
    for (int s = 0; s < ITEMS; s++) {
#pragma unroll
        for (int k = 0; k < 4; k++)
            v[s][k] = __ldcs(x + base0 + s * SSTRIDE + k * plane);
    }

    // Filter coeffs loaded after global loads issue (L1-broadcast, cheap)
    float fk[16];
#pragma unroll
    for (int q = 0; q < 16; q++) fk[q] = __ldg(filt + q);

#pragma unroll
    for (int s = 0; s < ITEMS; s++) {
        float o[4];
#pragma unroll
        for (int m = 0; m < 4; m++) {
            float acc = v[s][0] * fk[m];
            acc = fmaf(v[s][1], fk[4 + m], acc);
            acc = fmaf(v[s][2], fk[8 + m], acc);
            acc = fmaf(v[s][3], fk[12 + m], acc);
            o[m] = acc;
        }
        __stcs(out + ob0 + s * OSTRIDE, make_float4(o[0], o[1], o[2], o[3]));
    }
}

extern "C" void kernel_launch(void* const* d_in, const int* in_sizes, int n_in,
                              void* d_out, int out_size)
{
    const float* x    = (const float*)d_in[0];
    const float* filt = (const float*)d_in[1];
    float4*      out  = (float4*)d_out;

    const int blocks = CHUNK / BDIM;          // 8192
    idwt2d_kernel<<<blocks, BDIM>>>(x, filt, out);
}